// round 1
// baseline (speedup 1.0000x reference)
#include <cuda_runtime.h>

#define B_   16
#define C_   512
#define HD_  48
#define HW_  2304          // 48*48
#define LT_  18            // number of 128-wide l tiles (2304/128)
#define EPSF 1e-6f

// Scratch (device globals; no allocations in kernel_launch)
__device__ float  g_fA[(size_t)B_ * C_ * HW_];        // transposed A: [b][c][w*48+h]
__device__ float  g_partial[(size_t)B_ * LT_ * HW_];  // per-(b, l-tile) partial sum of squares per k
__device__ float4 g_inv4[B_ * HW_ / 4];               // rsqrt(sumsq+eps) per (b,k)

// ---------------------------------------------------------------------------
// 1) Transpose last two dims of A: g_fA[b][c][w*48+h] = A[b][c][h*48+w]
//    One block per (b,c) 48x48 tile.
// ---------------------------------------------------------------------------
__global__ void transpose_kernel(const float* __restrict__ A) {
    __shared__ float tile[48][49];
    int bc = blockIdx.x;
    const float* src = A + (size_t)bc * HW_;
    float* dst = g_fA + (size_t)bc * HW_;
    for (int i = threadIdx.x; i < HW_; i += blockDim.x)
        tile[i / 48][i % 48] = src[i];          // tile[h][w]
    __syncthreads();
    for (int i = threadIdx.x; i < HW_; i += blockDim.x)
        dst[i] = tile[i % 48][i / 48];          // i = w*48 + h -> A[h][w]
}

// ---------------------------------------------------------------------------
// 2) GEMM: out[b][l][k] = relu( sum_c g_fA[b][c][l] * Bf[b][c][k] )
//    128x128 tile, BK=16, 256 threads, 8x8 per thread.
//    Also emits per-k partial sum of squares (over this CTA's 128 l-rows).
// ---------------------------------------------------------------------------
__global__ __launch_bounds__(256) void corr_gemm(const float* __restrict__ Bf,
                                                 float* __restrict__ out) {
    __shared__ float As[16][128];
    __shared__ float Bs[16][128];
    __shared__ float red[16][128];

    const int t  = threadIdx.x;
    const int tx = t & 15;          // k sub-tile
    const int ty = t >> 4;          // l sub-tile
    const int kt = blockIdx.x, lt = blockIdx.y, b = blockIdx.z;
    const int l0 = lt * 128, k0 = kt * 128;

    const float* Ap = g_fA + (size_t)b * C_ * HW_;
    const float* Bp = Bf   + (size_t)b * C_ * HW_;

    float acc[8][8];
#pragma unroll
    for (int i = 0; i < 8; i++)
#pragma unroll
        for (int j = 0; j < 8; j++) acc[i][j] = 0.f;

    for (int c0 = 0; c0 < C_; c0 += 16) {
#pragma unroll
        for (int q = 0; q < 2; q++) {
            int id  = t * 2 + q;          // 0..511
            int kk  = id >> 5;
            int m4  = (id & 31) << 2;
            ((float4*)As)[id] = *(const float4*)(Ap + (size_t)(c0 + kk) * HW_ + l0 + m4);
            ((float4*)Bs)[id] = *(const float4*)(Bp + (size_t)(c0 + kk) * HW_ + k0 + m4);
        }
        __syncthreads();
#pragma unroll
        for (int kk = 0; kk < 16; kk++) {
            float a[8], bb[8];
            *(float4*)(a)      = *(const float4*)&As[kk][ty * 8];
            *(float4*)(a + 4)  = *(const float4*)&As[kk][ty * 8 + 4];
            *(float4*)(bb)     = *(const float4*)&Bs[kk][tx * 8];
            *(float4*)(bb + 4) = *(const float4*)&Bs[kk][tx * 8 + 4];
#pragma unroll
            for (int i = 0; i < 8; i++)
#pragma unroll
                for (int j = 0; j < 8; j++)
                    acc[i][j] += a[i] * bb[j];
        }
        __syncthreads();
    }

    // Epilogue: relu + transposed store + per-k sum of squares
    float ssq[8];
#pragma unroll
    for (int j = 0; j < 8; j++) ssq[j] = 0.f;

    const size_t outbase = (size_t)b * HW_ * HW_;
#pragma unroll
    for (int i = 0; i < 8; i++) {
        int l = l0 + ty * 8 + i;
        float* orow = out + outbase + (size_t)l * HW_ + k0 + tx * 8;
        float4 v0, v1;
        v0.x = fmaxf(acc[i][0], 0.f); v0.y = fmaxf(acc[i][1], 0.f);
        v0.z = fmaxf(acc[i][2], 0.f); v0.w = fmaxf(acc[i][3], 0.f);
        v1.x = fmaxf(acc[i][4], 0.f); v1.y = fmaxf(acc[i][5], 0.f);
        v1.z = fmaxf(acc[i][6], 0.f); v1.w = fmaxf(acc[i][7], 0.f);
        ssq[0] += v0.x * v0.x; ssq[1] += v0.y * v0.y;
        ssq[2] += v0.z * v0.z; ssq[3] += v0.w * v0.w;
        ssq[4] += v1.x * v1.x; ssq[5] += v1.y * v1.y;
        ssq[6] += v1.z * v1.z; ssq[7] += v1.w * v1.w;
        *(float4*)orow       = v0;
        *(float4*)(orow + 4) = v1;
    }

    __syncthreads();   // reuse red[] safely (distinct from As/Bs, but order anyway)
#pragma unroll
    for (int j = 0; j < 8; j++) red[ty][tx * 8 + j] = ssq[j];
    __syncthreads();

    if (t < 128) {
        float s = 0.f;
#pragma unroll
        for (int r = 0; r < 16; r++) s += red[r][t];
        g_partial[((size_t)b * LT_ + lt) * HW_ + k0 + t] = s;
    }
}

// ---------------------------------------------------------------------------
// 3) Reduce 18 partials per (b,k) -> rsqrt(sum + eps). Deterministic.
// ---------------------------------------------------------------------------
__global__ void reduce_kernel() {
    int i = blockIdx.x * blockDim.x + threadIdx.x;   // < B_*HW_
    int b = i / HW_;
    int k = i - b * HW_;
    float s = 0.f;
#pragma unroll
    for (int lt = 0; lt < LT_; lt++)
        s += g_partial[((size_t)b * LT_ + lt) * HW_ + k];
    ((float*)g_inv4)[i] = rsqrtf(s + EPSF);
}

// ---------------------------------------------------------------------------
// 4) Scale output rows by per-(b,k) inverse norm. float4 vectorized.
// ---------------------------------------------------------------------------
__global__ void normalize_kernel(float* __restrict__ out) {
    const size_t per_b = (size_t)HW_ * HW_ / 4;        // float4 per batch
    size_t i4 = (size_t)blockIdx.x * blockDim.x + threadIdx.x;
    int b = (int)(i4 / per_b);
    size_t rem = i4 - (size_t)b * per_b;
    int k4 = (int)(rem % (HW_ / 4));
    float4 inv = g_inv4[b * (HW_ / 4) + k4];
    float4* p = (float4*)out + i4;
    float4 v = *p;
    v.x *= inv.x; v.y *= inv.y; v.z *= inv.z; v.w *= inv.w;
    *p = v;
}

// ---------------------------------------------------------------------------
extern "C" void kernel_launch(void* const* d_in, const int* in_sizes, int n_in,
                              void* d_out, int out_size) {
    const float* A  = (const float*)d_in[0];
    const float* Bf = (const float*)d_in[1];
    float* out = (float*)d_out;

    transpose_kernel<<<B_ * C_, 256>>>(A);

    dim3 g(HW_ / 128, HW_ / 128, B_);
    corr_gemm<<<g, 256>>>(Bf, out);

    reduce_kernel<<<(B_ * HW_) / 256, 256>>>();

    unsigned n4blocks = (unsigned)(((size_t)B_ * HW_ * HW_ / 4) / 256);
    normalize_kernel<<<n4blocks, 256>>>(out);
}

// round 10
// speedup vs baseline: 1.5535x; 1.5535x over previous
#include <cuda_runtime.h>
#include <cuda_bf16.h>
#include <cstdint>

#define B_   16
#define C_   512
#define HW_  2304          // 48*48
#define EPSF 1e-6f

// ---- scratch: SAME footprint class as the proven-passing R1 (75.6 MB) -----
__device__ float  g_fA[(size_t)B_ * C_ * HW_];   // transposed A: [b][c][w*48+h]
__device__ float4 g_inv4[B_ * HW_ / 4];

// ---------------- PTX helpers (compute_100-baseline only) ------------------
__device__ __forceinline__ uint32_t smem_u32(const void* p) {
    uint32_t a;
    asm("{ .reg .u64 t; cvta.to.shared.u64 t, %1; cvt.u32.u64 %0, t; }" : "=r"(a) : "l"(p));
    return a;
}
__device__ __forceinline__ void cp16(uint32_t s, const void* g) {
    asm volatile("cp.async.cg.shared.global [%0], [%1], 16;" :: "r"(s), "l"(g) : "memory");
}
__device__ __forceinline__ void cp_commit() {
    asm volatile("cp.async.commit_group;" ::: "memory");
}
template <int N> __device__ __forceinline__ void cp_wait() {
    asm volatile("cp.async.wait_group %0;" :: "n"(N) : "memory");
}
__device__ __forceinline__ void ldsm4t(uint32_t* r, uint32_t a) {
    asm volatile("ldmatrix.sync.aligned.m8n8.x4.trans.shared.b16 {%0,%1,%2,%3}, [%4];"
                 : "=r"(r[0]), "=r"(r[1]), "=r"(r[2]), "=r"(r[3]) : "r"(a));
}
__device__ __forceinline__ void mma16816(float* d, const uint32_t* a, const uint32_t* b) {
    asm volatile(
        "mma.sync.aligned.m16n8k16.row.col.f32.bf16.bf16.f32 "
        "{%0,%1,%2,%3}, {%4,%5,%6,%7}, {%8,%9}, {%0,%1,%2,%3};"
        : "+f"(d[0]), "+f"(d[1]), "+f"(d[2]), "+f"(d[3])
        : "r"(a[0]), "r"(a[1]), "r"(a[2]), "r"(a[3]), "r"(b[0]), "r"(b[1]));
}
// pack two fp32 -> bf16x2 (elem0 in low half)
__device__ __forceinline__ uint32_t packbf(float e0, float e1) {
    uint32_t u;
    asm("cvt.rn.bf16x2.f32 %0, %1, %2;" : "=r"(u) : "f"(e1), "f"(e0));
    return u;
}

// ---------------------------------------------------------------------------
// 1) Transpose last two dims of A (R1-proven kernel, verbatim).
// ---------------------------------------------------------------------------
__global__ void transpose_kernel(const float* __restrict__ A) {
    __shared__ float tile[48][49];
    int bc = blockIdx.x;
    const float* src = A + (size_t)bc * HW_;
    float* dst = g_fA + (size_t)bc * HW_;
    for (int i = threadIdx.x; i < HW_; i += blockDim.x)
        tile[i / 48][i % 48] = src[i];
    __syncthreads();
    for (int i = threadIdx.x; i < HW_; i += blockDim.x)
        dst[i] = tile[i % 48][i / 48];
}

// ---------------------------------------------------------------------------
// 2) GEMM with in-kernel bf16 hi/lo split (3-term), mma.sync + ldmatrix.trans
//    CTA 128x128, BK=16, fp32 + bf16 tiles both double-buffered (64KB dyn).
//    512 threads, 16 warps (4x4), warp tile 32x32.
// ---------------------------------------------------------------------------
#define BM  128
#define BN  128
#define BK  16
#define NCH (C_ / BK)          // 32
// smem offsets
#define F32A(s) ((s) * 8192)               //  2 x 8KB fp32 A
#define F32B(s) (16384 + (s) * 8192)       //  2 x 8KB fp32 B
#define BF(s)   (32768 + (s) * 16384)      //  2 x 16KB bf16 tiles
#define BF_AHI  0
#define BF_ALO  4096
#define BF_BHI  8192
#define BF_BLO  12288
#define SMEM_TOT 65536

// bf16 tile: 16 rows x 128 cols, 256B/row; 16B chunk XOR-swizzled by row&7
#define BSWZ(row, colchunk) ((row) * 256 + ((((colchunk)) ^ ((row) & 7)) << 4))

__global__ __launch_bounds__(512, 1) void corr_gemm(const float* __restrict__ Bf,
                                                    float* __restrict__ out) {
    extern __shared__ char smem[];
    const uint32_t sb = smem_u32(smem);
    const int tid = threadIdx.x;
    const int wid = tid >> 5, ln = tid & 31;
    const int wm = wid >> 2, wn = wid & 3;       // 4 x 4 warp grid

    const int kt = blockIdx.x, lt = blockIdx.y, b = blockIdx.z;
    const int k0 = kt * BN, l0 = lt * BM;

    const float* Abase = g_fA + (size_t)b * C_ * HW_ + l0;
    const float* Bbase = Bf   + (size_t)b * C_ * HW_ + k0;

    // cp.async: 512 fp32 16B-chunks per operand per chunk; 1 A + 1 B per thread
    const int crow = tid >> 5;                 // 0..15 (c within chunk)
    const int ccc  = tid & 31;                 // 16B chunk within 512B row
    const uint32_t f32off = crow * 512 + ccc * 16;
    const size_t   goff   = (size_t)crow * HW_ + ccc * 4;

    // convert assignment: t<256 -> A, else B; 8 floats each
    const int cvhalf = tid >> 8;
    const int cq = tid & 255;
    const int cvr = cq >> 4;                   // row 0..15
    const int cvc = cq & 15;                   // 16B chunk (8 floats -> 8 bf16)
    const uint32_t cv_f32 = (cvhalf ? 16384u : 0u) + cvr * 512 + cvc * 32;
    const uint32_t cv_bf  = (cvhalf ? (uint32_t)BF_BHI : (uint32_t)BF_AHI) + BSWZ(cvr, cvc);

    float acc[2][4][4];
#pragma unroll
    for (int i = 0; i < 2; i++)
#pragma unroll
        for (int j = 0; j < 4; j++)
#pragma unroll
            for (int q = 0; q < 4; q++) acc[i][j][q] = 0.f;

#define LOAD_STAGE(CH) do {                                                    \
        uint32_t s_ = sb + ((CH) & 1) * 8192 + f32off;                         \
        size_t g_ = goff + (size_t)(CH) * BK * HW_;                            \
        cp16(s_,          Abase + g_);                                         \
        cp16(s_ + 16384,  Bbase + g_);                                         \
    } while (0)

    LOAD_STAGE(0); cp_commit();
    LOAD_STAGE(1); cp_commit();

    // ldmatrix.trans address offsets (within a bf16 tile)
    const int g8 = ln >> 3, l7 = ln & 7;
    const int akrow = (g8 >> 1) * 8 + l7;
    const int amc   = wm * 32 + (g8 & 1) * 8;            // + mt*16
    const uint32_t aoff0 = BSWZ(akrow, (amc) >> 3);
    const uint32_t aoff1 = BSWZ(akrow, (amc + 16) >> 3);
    const int bkrow = (g8 & 1) * 8 + l7;
    const int bnc   = wn * 32 + (g8 >> 1) * 8;           // + p*16
    const uint32_t boff0 = BSWZ(bkrow, (bnc) >> 3);
    const uint32_t boff1 = BSWZ(bkrow, (bnc + 16) >> 3);

    for (int ch = 0; ch < NCH; ch++) {
        cp_wait<1>();
        __syncthreads();

        // ---- convert fp32 stage -> bf16 hi/lo tiles ----
        {
            const char* fp = smem + (ch & 1) * 8192 + cv_f32;
            float4 v0 = *(const float4*)(fp);
            float4 v1 = *(const float4*)(fp + 16);
            uint32_t h0 = packbf(v0.x, v0.y);
            uint32_t h1 = packbf(v0.z, v0.w);
            uint32_t h2 = packbf(v1.x, v1.y);
            uint32_t h3 = packbf(v1.z, v1.w);
            uint32_t l0r = packbf(v0.x - __uint_as_float(h0 << 16),
                                  v0.y - __uint_as_float(h0 & 0xffff0000u));
            uint32_t l1r = packbf(v0.z - __uint_as_float(h1 << 16),
                                  v0.w - __uint_as_float(h1 & 0xffff0000u));
            uint32_t l2r = packbf(v1.x - __uint_as_float(h2 << 16),
                                  v1.y - __uint_as_float(h2 & 0xffff0000u));
            uint32_t l3r = packbf(v1.z - __uint_as_float(h3 << 16),
                                  v1.w - __uint_as_float(h3 & 0xffff0000u));
            char* bp = smem + BF(ch & 1) + cv_bf;
            *(uint4*)(bp)        = make_uint4(h0, h1, h2, h3);
            *(uint4*)(bp + 4096) = make_uint4(l0r, l1r, l2r, l3r);
        }
        __syncthreads();

        if (ch + 2 < NCH) LOAD_STAGE(ch + 2);
        cp_commit();

        // ---- fragments + 24 MMAs ----
        const uint32_t bf = sb + BF(ch & 1);
        uint32_t ah0[4], ah1[4], al0[4], al1[4], bb[4];
        ldsm4t(ah0, bf + BF_AHI + aoff0);
        ldsm4t(ah1, bf + BF_AHI + aoff1);
        ldsm4t(al0, bf + BF_ALO + aoff0);
        ldsm4t(al1, bf + BF_ALO + aoff1);
#pragma unroll
        for (int p = 0; p < 2; p++) {
            const uint32_t bo = p ? boff1 : boff0;
            ldsm4t(bb, bf + BF_BHI + bo);
            mma16816(acc[0][2 * p],     ah0, bb);
            mma16816(acc[0][2 * p + 1], ah0, bb + 2);
            mma16816(acc[1][2 * p],     ah1, bb);
            mma16816(acc[1][2 * p + 1], ah1, bb + 2);
            mma16816(acc[0][2 * p],     al0, bb);
            mma16816(acc[0][2 * p + 1], al0, bb + 2);
            mma16816(acc[1][2 * p],     al1, bb);
            mma16816(acc[1][2 * p + 1], al1, bb + 2);
            ldsm4t(bb, bf + BF_BLO + bo);
            mma16816(acc[0][2 * p],     ah0, bb);
            mma16816(acc[0][2 * p + 1], ah0, bb + 2);
            mma16816(acc[1][2 * p],     ah1, bb);
            mma16816(acc[1][2 * p + 1], ah1, bb + 2);
        }
    }

    // Epilogue: ReLU + direct coalesced store (out is [l][k])
    const size_t obase = (size_t)b * HW_ * HW_;
#pragma unroll
    for (int mt = 0; mt < 2; mt++) {
        int l_lo = l0 + wm * 32 + mt * 16 + (ln >> 2);
#pragma unroll
        for (int nt = 0; nt < 4; nt++) {
            int kcol = k0 + wn * 32 + nt * 8 + (ln & 3) * 2;
            float2 v0, v1;
            v0.x = fmaxf(acc[mt][nt][0], 0.f);
            v0.y = fmaxf(acc[mt][nt][1], 0.f);
            v1.x = fmaxf(acc[mt][nt][2], 0.f);
            v1.y = fmaxf(acc[mt][nt][3], 0.f);
            *(float2*)(out + obase + (size_t)l_lo * HW_ + kcol)       = v0;
            *(float2*)(out + obase + (size_t)(l_lo + 8) * HW_ + kcol) = v1;
        }
    }
}

// ---------------------------------------------------------------------------
// 3) Column sum of squares over l (per b,k) -> rsqrt. Deterministic.
// ---------------------------------------------------------------------------
__global__ __launch_bounds__(256) void reduce_kernel(const float* __restrict__ out) {
    const int k = blockIdx.x * 256 + threadIdx.x;
    const int b = blockIdx.y;
    const float* p = out + (size_t)b * HW_ * HW_ + k;
    float s = 0.f;
#pragma unroll 8
    for (int l = 0; l < HW_; l++) {
        float v = p[(size_t)l * HW_];
        s += v * v;
    }
    ((float*)g_inv4)[b * HW_ + k] = rsqrtf(s + EPSF);
}

// ---------------------------------------------------------------------------
// 4) Scale rows by per-(b,k) inverse norm. float4 vectorized.
// ---------------------------------------------------------------------------
__global__ __launch_bounds__(256) void normalize_kernel(float* __restrict__ out) {
    const size_t per_b = (size_t)HW_ * HW_ / 4;
    size_t i4 = (size_t)blockIdx.x * blockDim.x + threadIdx.x;
    int b = (int)(i4 / per_b);
    size_t rem = i4 - (size_t)b * per_b;
    int k4 = (int)(rem % (HW_ / 4));
    float4 inv = g_inv4[b * (HW_ / 4) + k4];
    float4* p = (float4*)out + i4;
    float4 v = *p;
    v.x *= inv.x; v.y *= inv.y; v.z *= inv.z; v.w *= inv.w;
    *p = v;
}

// ---------------------------------------------------------------------------
extern "C" void kernel_launch(void* const* d_in, const int* in_sizes, int n_in,
                              void* d_out, int out_size) {
    const float* A  = (const float*)d_in[0];
    const float* Bf = (const float*)d_in[1];
    float* out = (float*)d_out;

    cudaFuncSetAttribute(corr_gemm, cudaFuncAttributeMaxDynamicSharedMemorySize, SMEM_TOT);

    transpose_kernel<<<B_ * C_, 256>>>(A);

    dim3 gg(HW_ / BN, HW_ / BM, B_);
    corr_gemm<<<gg, 512, SMEM_TOT>>>(Bf, out);

    dim3 rg(HW_ / 256, B_);
    reduce_kernel<<<rg, 256>>>(out);

    unsigned n4blocks = (unsigned)(((size_t)B_ * HW_ * HW_ / 4) / 256);
    normalize_kernel<<<n4blocks, 256>>>(out);
}

// round 11
// speedup vs baseline: 2.7345x; 1.7603x over previous
#include <cuda_runtime.h>
#include <cuda_bf16.h>
#include <cstdint>

#define B_   16
#define C_   512
#define HW_  2304              // 48*48
#define EPSF 1e-6f

#define PBSZ   9437184         // per-batch tile bytes (A 4.5MB + B 4.5MB)
#define A_SEC  4718592         // A section size within a batch (18*32*8192)
#define OFF_T  169869312       // byte offset of tile region in d_out (= half of out)

// ---- scratch: 75.5 + 2.65 MB ~= R1's proven-passing 78.3 MB ----
__device__ char  g_tiles[(size_t)8 * PBSZ];          // tiles for batches 8..15
__device__ float g_part[(size_t)B_ * 18 * HW_];      // per-(b,lt) partial ssq per k
__device__ float g_inv[(size_t)B_ * HW_];            // rsqrt per (b,k)

// ---------------- PTX helpers (compute_100-baseline only) ------------------
__device__ __forceinline__ uint32_t smem_u32(const void* p) {
    uint32_t a;
    asm("{ .reg .u64 t; cvta.to.shared.u64 t, %1; cvt.u32.u64 %0, t; }" : "=r"(a) : "l"(p));
    return a;
}
__device__ __forceinline__ void cp16(uint32_t s, const void* g) {
    asm volatile("cp.async.cg.shared.global [%0], [%1], 16;" :: "r"(s), "l"(g) : "memory");
}
__device__ __forceinline__ void cp_commit() {
    asm volatile("cp.async.commit_group;" ::: "memory");
}
template <int N> __device__ __forceinline__ void cp_wait() {
    asm volatile("cp.async.wait_group %0;" :: "n"(N) : "memory");
}
__device__ __forceinline__ void ldsm4t(uint32_t* r, uint32_t a) {
    asm volatile("ldmatrix.sync.aligned.m8n8.x4.trans.shared.b16 {%0,%1,%2,%3}, [%4];"
                 : "=r"(r[0]), "=r"(r[1]), "=r"(r[2]), "=r"(r[3]) : "r"(a));
}
__device__ __forceinline__ void mma16816(float* d, const uint32_t* a, const uint32_t* b) {
    asm volatile(
        "mma.sync.aligned.m16n8k16.row.col.f32.bf16.bf16.f32 "
        "{%0,%1,%2,%3}, {%4,%5,%6,%7}, {%8,%9}, {%0,%1,%2,%3};"
        : "+f"(d[0]), "+f"(d[1]), "+f"(d[2]), "+f"(d[3])
        : "r"(a[0]), "r"(a[1]), "r"(a[2]), "r"(a[3]), "r"(b[0]), "r"(b[1]));
}
// pack two fp32 -> bf16x2 (e0 in low half)
__device__ __forceinline__ uint32_t packbf(float e0, float e1) {
    uint32_t u;
    asm("cvt.rn.bf16x2.f32 %0, %1, %2;" : "=r"(u) : "f"(e1), "f"(e0));
    return u;
}
// bf16 tile: 16 rows(c) x 128 cols, 256B/row; 16B chunk XOR-swizzled (R10-proven)
#define BSWZ(row, colchunk) ((row) * 256 + ((((colchunk)) ^ ((row) & 7)) << 4))

// ---------------------------------------------------------------------------
// 1) Prep: build ldsm-ready hi/lo bf16 tile images for one operand.
//    Tile (b, t, ch) = [c 16 rows][l 128 cols]: hi 4KB + lo 4KB, swizzled.
//    For A (PERM): l = (i%48)*48 + i/48 (w-major flatten); for B: l = i.
//    CTA = (4-channel block, b). Batches 0..7 -> dst0 (d_out tail), 8..15 -> dst1.
// ---------------------------------------------------------------------------
template <bool PERM>
__global__ __launch_bounds__(256) void prep_kernel(const float* __restrict__ src,
                                                   char* dst0, char* dst1, int sec) {
    __shared__ float sm[4][2352];           // 2304 + pad(l/48): conflict-free
    const int tid = threadIdx.x;
    const int c0 = blockIdx.x * 4, b = blockIdx.y;
    char* base = (b < 8 ? dst0 + (size_t)b * PBSZ
                        : dst1 + (size_t)(b - 8) * PBSZ) + sec;

#pragma unroll
    for (int cc = 0; cc < 4; cc++) {
        const float* s = src + (size_t)(b * C_ + c0 + cc) * HW_;
        for (int i = tid; i < HW_; i += 256) {
            int l = PERM ? ((i % 48) * 48 + i / 48) : i;
            sm[cc][l + l / 48] = s[i];
        }
    }
    __syncthreads();

    for (int idx = tid; idx < 1152; idx += 256) {   // 18 lt * 4 cc * 16 chunks
        int lt = idx / 64, r = idx & 63;
        int cc = r >> 4, chk = r & 15;
        int c = c0 + cc, row = c & 15, ch = c >> 4;
        char* tb = base + (size_t)(lt * 32 + ch) * 8192;
        int l0 = lt * 128 + chk * 8;
        float f[8];
#pragma unroll
        for (int e = 0; e < 8; e++) { int l = l0 + e; f[e] = sm[cc][l + l / 48]; }
        uint32_t h[4], lo[4];
#pragma unroll
        for (int q = 0; q < 4; q++) {
            h[q] = packbf(f[2 * q], f[2 * q + 1]);
            lo[q] = packbf(f[2 * q]     - __uint_as_float(h[q] << 16),
                           f[2 * q + 1] - __uint_as_float(h[q] & 0xffff0000u));
        }
        uint32_t off = BSWZ(row, chk);
        *(uint4*)(tb + off)        = make_uint4(h[0], h[1], h[2], h[3]);
        *(uint4*)(tb + 4096 + off) = make_uint4(lo[0], lo[1], lo[2], lo[3]);
    }
}

// ---------------------------------------------------------------------------
// 2) Pure mma.sync GEMM on pre-tiled operands. CTA 128x128, BK=16, 4 stages.
//    256 threads, 8 warps (2x4), warp tile 64x32. Epilogue: ReLU + store +
//    deterministic per-k partial sum-of-squares.
// ---------------------------------------------------------------------------
#define NCH 32
#define STG 16384          // stage: Ahi 4K | Alo 4K | Bhi 4K | Blo 4K
#define SMEM_TOT (4 * STG) // 64KB

__global__ __launch_bounds__(256, 2) void corr_gemm(const char* tiles,
                                                    float* out, int b0) {
    extern __shared__ char smem[];
    const uint32_t sb = smem_u32(smem);
    const int tid = threadIdx.x;
    const int wid = tid >> 5, ln = tid & 31;
    const int wm = wid >> 2, wn = wid & 3;       // 2 x 4 warps

    const int kt = blockIdx.x, lt = blockIdx.y, z = blockIdx.z;
    const int b = b0 + z, k0 = kt * 128, l0 = lt * 128;

    const char* tA = tiles + (size_t)z * PBSZ + (size_t)(lt * 32) * 8192;
    const char* tB = tiles + (size_t)z * PBSZ + A_SEC + (size_t)(kt * 32) * 8192;

    float acc[4][4][4];
#pragma unroll
    for (int i = 0; i < 4; i++)
#pragma unroll
        for (int j = 0; j < 4; j++)
#pragma unroll
            for (int q = 0; q < 4; q++) acc[i][j][q] = 0.f;

#define LOAD_STAGE(CH) do {                                                    \
        uint32_t st_ = sb + ((CH) & 3) * STG;                                  \
        const char* a_ = tA + (size_t)(CH) * 8192;                             \
        const char* b_ = tB + (size_t)(CH) * 8192;                             \
        _Pragma("unroll")                                                      \
        for (int q_ = 0; q_ < 2; q_++) {                                       \
            int i_ = (tid + q_ * 256) * 16;                                    \
            cp16(st_ + i_,        a_ + i_);                                    \
            cp16(st_ + 8192 + i_, b_ + i_);                                    \
        }                                                                      \
    } while (0)

    LOAD_STAGE(0); cp_commit();
    LOAD_STAGE(1); cp_commit();
    LOAD_STAGE(2); cp_commit();

    // ldmatrix.trans addresses (R10-proven formulas)
    const int g8 = ln >> 3, l7 = ln & 7;
    const int akrow = (g8 >> 1) * 8 + l7;
    uint32_t aoff[4], boff[2];
#pragma unroll
    for (int mt = 0; mt < 4; mt++)
        aoff[mt] = BSWZ(akrow, (wm * 64 + mt * 16 + (g8 & 1) * 8) >> 3);
    const int bkrow = (g8 & 1) * 8 + l7;
#pragma unroll
    for (int p = 0; p < 2; p++)
        boff[p] = BSWZ(bkrow, (wn * 32 + p * 16 + (g8 >> 1) * 8) >> 3);

    for (int ch = 0; ch < NCH; ch++) {
        cp_wait<2>();
        __syncthreads();
        if (ch + 3 < NCH) LOAD_STAGE(ch + 3);
        cp_commit();

        const uint32_t st = sb + (ch & 3) * STG;
        uint32_t bh0[4], bh1[4], bl0[4], bl1[4];
        ldsm4t(bh0, st + 8192  + boff[0]);
        ldsm4t(bh1, st + 8192  + boff[1]);
        ldsm4t(bl0, st + 12288 + boff[0]);
        ldsm4t(bl1, st + 12288 + boff[1]);
#pragma unroll
        for (int half = 0; half < 2; half++) {
            const int m0 = half * 2;
            uint32_t ah0[4], ah1[4], al0[4], al1[4];
            ldsm4t(ah0, st + aoff[m0]);
            ldsm4t(ah1, st + aoff[m0 + 1]);
            ldsm4t(al0, st + 4096 + aoff[m0]);
            ldsm4t(al1, st + 4096 + aoff[m0 + 1]);
            mma16816(acc[m0][0],     ah0, bh0); mma16816(acc[m0][1],     ah0, bh0 + 2);
            mma16816(acc[m0][2],     ah0, bh1); mma16816(acc[m0][3],     ah0, bh1 + 2);
            mma16816(acc[m0 + 1][0], ah1, bh0); mma16816(acc[m0 + 1][1], ah1, bh0 + 2);
            mma16816(acc[m0 + 1][2], ah1, bh1); mma16816(acc[m0 + 1][3], ah1, bh1 + 2);
            mma16816(acc[m0][0],     al0, bh0); mma16816(acc[m0][1],     al0, bh0 + 2);
            mma16816(acc[m0][2],     al0, bh1); mma16816(acc[m0][3],     al0, bh1 + 2);
            mma16816(acc[m0 + 1][0], al1, bh0); mma16816(acc[m0 + 1][1], al1, bh0 + 2);
            mma16816(acc[m0 + 1][2], al1, bh1); mma16816(acc[m0 + 1][3], al1, bh1 + 2);
            mma16816(acc[m0][0],     ah0, bl0); mma16816(acc[m0][1],     ah0, bl0 + 2);
            mma16816(acc[m0][2],     ah0, bl1); mma16816(acc[m0][3],     ah0, bl1 + 2);
            mma16816(acc[m0 + 1][0], ah1, bl0); mma16816(acc[m0 + 1][1], ah1, bl0 + 2);
            mma16816(acc[m0 + 1][2], ah1, bl1); mma16816(acc[m0 + 1][3], ah1, bl1 + 2);
        }
    }
    cp_wait<0>();

    // Epilogue: ReLU + store + per-thread ssq over its 8 columns
    float ssq[8];
#pragma unroll
    for (int q = 0; q < 8; q++) ssq[q] = 0.f;

    const size_t obase = (size_t)b * HW_ * HW_;
#pragma unroll
    for (int mt = 0; mt < 4; mt++) {
        int l_lo = l0 + wm * 64 + mt * 16 + (ln >> 2);
#pragma unroll
        for (int nt = 0; nt < 4; nt++) {
            int kcol = k0 + wn * 32 + nt * 8 + (ln & 3) * 2;
            float2 v0, v1;
            v0.x = fmaxf(acc[mt][nt][0], 0.f);
            v0.y = fmaxf(acc[mt][nt][1], 0.f);
            v1.x = fmaxf(acc[mt][nt][2], 0.f);
            v1.y = fmaxf(acc[mt][nt][3], 0.f);
            ssq[nt * 2]     += v0.x * v0.x + v1.x * v1.x;
            ssq[nt * 2 + 1] += v0.y * v0.y + v1.y * v1.y;
            *(float2*)(out + obase + (size_t)l_lo * HW_ + kcol)       = v0;
            *(float2*)(out + obase + (size_t)(l_lo + 8) * HW_ + kcol) = v1;
        }
    }

    // Deterministic CTA reduction: red[col 0..127][slot 0..15]
    __syncthreads();
    float* red = (float*)smem;
    const int slot = wm * 8 + (ln >> 2);
#pragma unroll
    for (int nt = 0; nt < 4; nt++)
#pragma unroll
        for (int e = 0; e < 2; e++) {
            int col = wn * 32 + nt * 8 + (ln & 3) * 2 + e;
            red[col * 17 + slot] = ssq[nt * 2 + e];
        }
    __syncthreads();
    if (tid < 128) {
        float s = 0.f;
#pragma unroll
        for (int r = 0; r < 16; r++) s += red[tid * 17 + r];
        g_part[((size_t)b * 18 + lt) * HW_ + k0 + tid] = s;
    }
}

// ---------------------------------------------------------------------------
// 3) Reduce 18 partials per (b,k) -> rsqrt. Deterministic.
// ---------------------------------------------------------------------------
__global__ __launch_bounds__(256) void reduce2_kernel() {
    int i = blockIdx.x * 256 + threadIdx.x;          // < 16*2304
    int b = i / HW_, k = i - b * HW_;
    float s = 0.f;
#pragma unroll
    for (int lt = 0; lt < 18; lt++)
        s += g_part[((size_t)b * 18 + lt) * HW_ + k];
    g_inv[i] = rsqrtf(s + EPSF);
}

// ---------------------------------------------------------------------------
// 4) Scale rows by per-(b,k) inverse norm. float4 vectorized.
// ---------------------------------------------------------------------------
__global__ __launch_bounds__(256) void normalize_kernel(float* __restrict__ out) {
    const size_t per_b = (size_t)HW_ * HW_ / 4;
    size_t i4 = (size_t)blockIdx.x * blockDim.x + threadIdx.x;
    int b = (int)(i4 / per_b);
    size_t rem = i4 - (size_t)b * per_b;
    int k4 = (int)(rem % (HW_ / 4));
    float4 inv = ((const float4*)g_inv)[b * (HW_ / 4) + k4];
    float4* p = (float4*)out + i4;
    float4 v = *p;
    v.x *= inv.x; v.y *= inv.y; v.z *= inv.z; v.w *= inv.w;
    *p = v;
}

// ---------------------------------------------------------------------------
extern "C" void kernel_launch(void* const* d_in, const int* in_sizes, int n_in,
                              void* d_out, int out_size) {
    const float* A  = (const float*)d_in[0];
    const float* Bf = (const float*)d_in[1];
    float* out = (float*)d_out;

    cudaFuncSetAttribute(corr_gemm, cudaFuncAttributeMaxDynamicSharedMemorySize, SMEM_TOT);

    char* dt = (char*)d_out + OFF_T;    // tiles for batches 0..7 (in out[8..15] region)
    void* gt = nullptr;
    cudaGetSymbolAddress(&gt, g_tiles); // tiles for batches 8..15

    dim3 pg(C_ / 4, B_);
    prep_kernel<true ><<<pg, 256>>>(A,  dt, (char*)gt, 0);       // A tiles
    prep_kernel<false><<<pg, 256>>>(Bf, dt, (char*)gt, A_SEC);   // B tiles

    dim3 gg(18, 18, 8);
    corr_gemm<<<gg, 256, SMEM_TOT>>>(dt, out, 0);        // b=0..7: read d_out tail, write head
    corr_gemm<<<gg, 256, SMEM_TOT>>>((char*)gt, out, 8); // b=8..15: read globals, write tail

    reduce2_kernel<<<(B_ * HW_) / 256, 256>>>();

    unsigned n4blocks = (unsigned)(((size_t)B_ * HW_ * HW_ / 4) / 256);
    normalize_kernel<<<n4blocks, 256>>>(out);
}

// round 12
// speedup vs baseline: 5.0739x; 1.8555x over previous
#include <cuda_runtime.h>
#include <cuda_fp16.h>
#include <cstdint>

#define B_   16
#define C_   512
#define HW_  2304              // 48*48
#define EPSF 1e-6f

#define PBSZ   4718592         // per-batch tile bytes (A 2.25MB + B 2.25MB)
#define A_SEC  2359296         // A section size within a batch (18*32*4096)

// ---- scratch: 72 + 2.65 MB = 74.8 MB (< proven-passing 78.3 MB BSS) ----
__device__ char  g_tiles[(size_t)B_ * PBSZ];         // fp16 tiles, all 16 batches
__device__ float g_part[(size_t)B_ * 18 * HW_];      // per-(b,lt) partial ssq per k
__device__ float g_inv[(size_t)B_ * HW_];            // rsqrt per (b,k)

// ---------------- PTX helpers (compute_100-baseline only) ------------------
__device__ __forceinline__ uint32_t smem_u32(const void* p) {
    uint32_t a;
    asm("{ .reg .u64 t; cvta.to.shared.u64 t, %1; cvt.u32.u64 %0, t; }" : "=r"(a) : "l"(p));
    return a;
}
__device__ __forceinline__ void cp16(uint32_t s, const void* g) {
    asm volatile("cp.async.cg.shared.global [%0], [%1], 16;" :: "r"(s), "l"(g) : "memory");
}
__device__ __forceinline__ void cp_commit() {
    asm volatile("cp.async.commit_group;" ::: "memory");
}
template <int N> __device__ __forceinline__ void cp_wait() {
    asm volatile("cp.async.wait_group %0;" :: "n"(N) : "memory");
}
__device__ __forceinline__ void ldsm4t(uint32_t* r, uint32_t a) {
    asm volatile("ldmatrix.sync.aligned.m8n8.x4.trans.shared.b16 {%0,%1,%2,%3}, [%4];"
                 : "=r"(r[0]), "=r"(r[1]), "=r"(r[2]), "=r"(r[3]) : "r"(a));
}
__device__ __forceinline__ void mma16816(float* d, const uint32_t* a, const uint32_t* b) {
    asm volatile(
        "mma.sync.aligned.m16n8k16.row.col.f32.f16.f16.f32 "
        "{%0,%1,%2,%3}, {%4,%5,%6,%7}, {%8,%9}, {%0,%1,%2,%3};"
        : "+f"(d[0]), "+f"(d[1]), "+f"(d[2]), "+f"(d[3])
        : "r"(a[0]), "r"(a[1]), "r"(a[2]), "r"(a[3]), "r"(b[0]), "r"(b[1]));
}
// pack two fp32 -> f16x2 (e0 in low half)
__device__ __forceinline__ uint32_t packh(float e0, float e1) {
    uint32_t u;
    asm("cvt.rn.f16x2.f32 %0, %1, %2;" : "=r"(u) : "f"(e1), "f"(e0));
    return u;
}
// fp16 tile: 16 rows(c) x 128 cols, 256B/row; 16B chunk XOR-swizzled (proven)
#define BSWZ(row, colchunk) ((row) * 256 + ((((colchunk)) ^ ((row) & 7)) << 4))

// ---------------------------------------------------------------------------
// 1) Prep: build ldsm-ready fp16 tile images for one operand.
//    Tile (b, lt, ch) = [c 16 rows][l 128 cols] = 4KB, swizzled.
//    For A (PERM): l = (i%48)*48 + i/48 (w-major flatten); for B: l = i.
// ---------------------------------------------------------------------------
template <bool PERM>
__global__ __launch_bounds__(256) void prep_kernel(const float* __restrict__ src,
                                                   int sec) {
    __shared__ float sm[4][2352];           // 2304 + pad(l/48): conflict-free
    const int tid = threadIdx.x;
    const int c0 = blockIdx.x * 4, b = blockIdx.y;
    char* base = g_tiles + (size_t)b * PBSZ + sec;

#pragma unroll
    for (int cc = 0; cc < 4; cc++) {
        const float* s = src + (size_t)(b * C_ + c0 + cc) * HW_;
        for (int i = tid; i < HW_; i += 256) {
            int l = PERM ? ((i % 48) * 48 + i / 48) : i;
            sm[cc][l + l / 48] = s[i];
        }
    }
    __syncthreads();

    for (int idx = tid; idx < 1152; idx += 256) {   // 18 lt * 4 cc * 16 chunks
        int lt = idx / 64, r = idx & 63;
        int cc = r >> 4, chk = r & 15;
        int c = c0 + cc, row = c & 15, ch = c >> 4;
        char* tb = base + (size_t)(lt * 32 + ch) * 4096;
        int l0 = lt * 128 + chk * 8;
        float f[8];
#pragma unroll
        for (int e = 0; e < 8; e++) { int l = l0 + e; f[e] = sm[cc][l + l / 48]; }
        uint32_t h[4];
#pragma unroll
        for (int q = 0; q < 4; q++) h[q] = packh(f[2 * q], f[2 * q + 1]);
        *(uint4*)(tb + BSWZ(row, chk)) = make_uint4(h[0], h[1], h[2], h[3]);
    }
}

// ---------------------------------------------------------------------------
// 2) Pure fp16 mma.sync GEMM on pre-tiled operands. CTA 128x128, BK=16,
//    4 stages x 8KB. 256 threads, 8 warps (2x4), warp tile 64x32 (16 MMAs/ch).
//    Epilogue: ReLU + store + deterministic per-k partial sum-of-squares.
// ---------------------------------------------------------------------------
#define NCH 32
#define STG 8192           // stage: Ah 4K | Bh 4K
#define SMEM_TOT (4 * STG) // 32KB

__global__ __launch_bounds__(256, 2) void corr_gemm(float* __restrict__ out) {
    extern __shared__ char smem[];
    const uint32_t sb = smem_u32(smem);
    const int tid = threadIdx.x;
    const int wid = tid >> 5, ln = tid & 31;
    const int wm = wid >> 2, wn = wid & 3;       // 2 x 4 warps

    const int kt = blockIdx.x, lt = blockIdx.y, b = blockIdx.z;
    const int k0 = kt * 128, l0 = lt * 128;

    const char* tA = g_tiles + (size_t)b * PBSZ + (size_t)(lt * 32) * 4096;
    const char* tB = g_tiles + (size_t)b * PBSZ + A_SEC + (size_t)(kt * 32) * 4096;

    float acc[4][4][4];
#pragma unroll
    for (int i = 0; i < 4; i++)
#pragma unroll
        for (int j = 0; j < 4; j++)
#pragma unroll
            for (int q = 0; q < 4; q++) acc[i][j][q] = 0.f;

#define LOAD_STAGE(CH) do {                                                    \
        uint32_t st_ = sb + ((CH) & 3) * STG + tid * 16;                       \
        cp16(st_,        tA + (size_t)(CH) * 4096 + tid * 16);                 \
        cp16(st_ + 4096, tB + (size_t)(CH) * 4096 + tid * 16);                 \
    } while (0)

    LOAD_STAGE(0); cp_commit();
    LOAD_STAGE(1); cp_commit();
    LOAD_STAGE(2); cp_commit();

    // ldmatrix.trans addresses (proven formulas)
    const int g8 = ln >> 3, l7 = ln & 7;
    const int akrow = (g8 >> 1) * 8 + l7;
    uint32_t aoff[4], boff[2];
#pragma unroll
    for (int mt = 0; mt < 4; mt++)
        aoff[mt] = BSWZ(akrow, (wm * 64 + mt * 16 + (g8 & 1) * 8) >> 3);
    const int bkrow = (g8 & 1) * 8 + l7;
#pragma unroll
    for (int p = 0; p < 2; p++)
        boff[p] = BSWZ(bkrow, (wn * 32 + p * 16 + (g8 >> 1) * 8) >> 3);

    for (int ch = 0; ch < NCH; ch++) {
        cp_wait<2>();
        __syncthreads();
        if (ch + 3 < NCH) LOAD_STAGE(ch + 3);
        cp_commit();

        const uint32_t st = sb + (ch & 3) * STG;
        uint32_t bb0[4], bb1[4];
        ldsm4t(bb0, st + 4096 + boff[0]);
        ldsm4t(bb1, st + 4096 + boff[1]);
#pragma unroll
        for (int mt = 0; mt < 4; mt++) {
            uint32_t aa[4];
            ldsm4t(aa, st + aoff[mt]);
            mma16816(acc[mt][0], aa, bb0);
            mma16816(acc[mt][1], aa, bb0 + 2);
            mma16816(acc[mt][2], aa, bb1);
            mma16816(acc[mt][3], aa, bb1 + 2);
        }
    }
    cp_wait<0>();

    // Epilogue: ReLU + store + per-thread ssq over its 8 columns
    float ssq[8];
#pragma unroll
    for (int q = 0; q < 8; q++) ssq[q] = 0.f;

    const size_t obase = (size_t)b * HW_ * HW_;
#pragma unroll
    for (int mt = 0; mt < 4; mt++) {
        int l_lo = l0 + wm * 64 + mt * 16 + (ln >> 2);
#pragma unroll
        for (int nt = 0; nt < 4; nt++) {
            int kcol = k0 + wn * 32 + nt * 8 + (ln & 3) * 2;
            float2 v0, v1;
            v0.x = fmaxf(acc[mt][nt][0], 0.f);
            v0.y = fmaxf(acc[mt][nt][1], 0.f);
            v1.x = fmaxf(acc[mt][nt][2], 0.f);
            v1.y = fmaxf(acc[mt][nt][3], 0.f);
            ssq[nt * 2]     += v0.x * v0.x + v1.x * v1.x;
            ssq[nt * 2 + 1] += v0.y * v0.y + v1.y * v1.y;
            *(float2*)(out + obase + (size_t)l_lo * HW_ + kcol)       = v0;
            *(float2*)(out + obase + (size_t)(l_lo + 8) * HW_ + kcol) = v1;
        }
    }

    // Deterministic CTA reduction: red[col 0..127][slot 0..15]
    __syncthreads();
    float* red = (float*)smem;
    const int slot = wm * 8 + (ln >> 2);
#pragma unroll
    for (int nt = 0; nt < 4; nt++)
#pragma unroll
        for (int e = 0; e < 2; e++) {
            int col = wn * 32 + nt * 8 + (ln & 3) * 2 + e;
            red[col * 17 + slot] = ssq[nt * 2 + e];
        }
    __syncthreads();
    if (tid < 128) {
        float s = 0.f;
#pragma unroll
        for (int r = 0; r < 16; r++) s += red[tid * 17 + r];
        g_part[((size_t)b * 18 + lt) * HW_ + k0 + tid] = s;
    }
}

// ---------------------------------------------------------------------------
// 3) Reduce 18 partials per (b,k) -> rsqrt. Deterministic.
// ---------------------------------------------------------------------------
__global__ __launch_bounds__(256) void reduce2_kernel() {
    int i = blockIdx.x * 256 + threadIdx.x;          // < 16*2304
    int b = i / HW_, k = i - b * HW_;
    float s = 0.f;
#pragma unroll
    for (int lt = 0; lt < 18; lt++)
        s += g_part[((size_t)b * 18 + lt) * HW_ + k];
    g_inv[i] = rsqrtf(s + EPSF);
}

// ---------------------------------------------------------------------------
// 4) Scale rows by per-(b,k) inverse norm. float4 vectorized.
// ---------------------------------------------------------------------------
__global__ __launch_bounds__(256) void normalize_kernel(float* __restrict__ out) {
    const size_t per_b = (size_t)HW_ * HW_ / 4;
    size_t i4 = (size_t)blockIdx.x * blockDim.x + threadIdx.x;
    int b = (int)(i4 / per_b);
    size_t rem = i4 - (size_t)b * per_b;
    int k4 = (int)(rem % (HW_ / 4));
    float4 inv = ((const float4*)g_inv)[b * (HW_ / 4) + k4];
    float4* p = (float4*)out + i4;
    float4 v = *p;
    v.x *= inv.x; v.y *= inv.y; v.z *= inv.z; v.w *= inv.w;
    *p = v;
}

// ---------------------------------------------------------------------------
extern "C" void kernel_launch(void* const* d_in, const int* in_sizes, int n_in,
                              void* d_out, int out_size) {
    const float* A  = (const float*)d_in[0];
    const float* Bf = (const float*)d_in[1];
    float* out = (float*)d_out;

    cudaFuncSetAttribute(corr_gemm, cudaFuncAttributeMaxDynamicSharedMemorySize, SMEM_TOT);

    dim3 pg(C_ / 4, B_);
    prep_kernel<true ><<<pg, 256>>>(A,  0);       // A tiles
    prep_kernel<false><<<pg, 256>>>(Bf, A_SEC);   // B tiles

    dim3 gg(18, 18, B_);
    corr_gemm<<<gg, 256, SMEM_TOT>>>(out);

    reduce2_kernel<<<(B_ * HW_) / 256, 256>>>();

    unsigned n4blocks = (unsigned)(((size_t)B_ * HW_ * HW_ / 4) / 256);
    normalize_kernel<<<n4blocks, 256>>>(out);
}